// round 5
// baseline (speedup 1.0000x reference)
#include <cuda_runtime.h>
#include <cuda_bf16.h>
#include <cstdint>

// Problem constants
#define NNODES 100000
#define DIM    256
#define NBASES 8
#define NRELS  16
#define NEDGES 800000

// ---------------------------------------------------------------------------
// Scratch (static device globals -- no runtime allocation allowed)
// Footprint deliberately minimized: 819.2 MB + 400 KB.
// ---------------------------------------------------------------------------
__device__ float g_Y[(size_t)NBASES * NNODES * DIM];   // Y[b] = emb @ basis[b]
__device__ float g_deg[NNODES];                        // in-degree counts

// ---------------------------------------------------------------------------
// Packed fp32x2 FMA (Blackwell FFMA2; only reachable via PTX)
// ---------------------------------------------------------------------------
struct F2u { union { float2 f; unsigned long long u; }; };

__device__ __forceinline__ void ffma2(unsigned long long& d,
                                      const unsigned long long a,
                                      const unsigned long long b) {
    asm("fma.rn.f32x2 %0, %1, %2, %0;" : "+l"(d) : "l"(a), "l"(b));
}

__device__ __forceinline__ void red_add_v4(float4* p, float4 v) {
    asm volatile("red.global.add.v4.f32 [%0], {%1, %2, %3, %4};"
                 :: "l"(p), "f"(v.x), "f"(v.y), "f"(v.z), "f"(v.w) : "memory");
}

// ---------------------------------------------------------------------------
// K0: zero the output accumulator and degree counters
// ---------------------------------------------------------------------------
__global__ void zero_kernel(float4* __restrict__ out) {
    size_t i = (size_t)blockIdx.x * blockDim.x + threadIdx.x;
    const size_t tot4 = (size_t)NNODES * DIM / 4;   // 6,400,000
    if (i < tot4) out[i] = make_float4(0.f, 0.f, 0.f, 0.f);
    if (i < NNODES) g_deg[i] = 0.f;
}

// ---------------------------------------------------------------------------
// K1: batched SGEMM  Y[b] = emb[node_ids] @ basis[b]
//     M=100000, N=256, K=256, batch=8.  128x128x8 tiles, 8x8/thread, FFMA2.
// ---------------------------------------------------------------------------
__global__ __launch_bounds__(256, 2)
void gemm_basis_kernel(const float* __restrict__ emb,
                       const int*   __restrict__ node_ids,
                       const float* __restrict__ basis) {
    const int b = blockIdx.z;
    const float* __restrict__ Bp = basis + (size_t)b * DIM * DIM;
    float* __restrict__ Yb = g_Y + (size_t)b * NNODES * DIM;

    __shared__ float As[8][128];
    __shared__ float Bs[8][128];
    __shared__ int   rowIdx[128];

    const int tid = threadIdx.x;
    const int m0 = blockIdx.x * 128;
    const int n0 = blockIdx.y * 128;

    if (tid < 128) {
        int r = m0 + tid;
        rowIdx[tid] = (r < NNODES) ? node_ids[r] : node_ids[0];
    }
    __syncthreads();

    const int tx = tid & 15;    // column group (8 cols each)
    const int ty = tid >> 4;    // row group    (8 rows each)

    const int aRow = tid >> 1;          // 0..127
    const int aCol = (tid & 1) * 4;     // 0 or 4
    const int bRow = tid >> 5;          // 0..7
    const int bCol = (tid & 31) * 4;    // 0..124

    const float* __restrict__ aPtr = emb + (size_t)rowIdx[aRow] * DIM + aCol;
    const float* __restrict__ bPtr = Bp + (size_t)bRow * DIM + n0 + bCol;

    F2u acc[8][4];
    #pragma unroll
    for (int i = 0; i < 8; i++)
        #pragma unroll
        for (int j = 0; j < 4; j++) acc[i][j].u = 0ull;

    for (int k0 = 0; k0 < DIM; k0 += 8) {
        // global loads overlap the previous tile's compute
        float4 av = *(const float4*)(aPtr + k0);
        float4 bv = *(const float4*)(bPtr + (size_t)k0 * DIM);
        __syncthreads();   // previous tile's smem reads done
        As[aCol + 0][aRow] = av.x;
        As[aCol + 1][aRow] = av.y;
        As[aCol + 2][aRow] = av.z;
        As[aCol + 3][aRow] = av.w;
        *(float4*)&Bs[bRow][bCol] = bv;
        __syncthreads();   // tile visible

        #pragma unroll
        for (int kk = 0; kk < 8; kk++) {
            F2u ad[8];
            #pragma unroll
            for (int i = 0; i < 8; i++) {
                float a = As[kk][ty * 8 + i];
                ad[i].f = make_float2(a, a);
            }
            F2u bp[4];
            #pragma unroll
            for (int j = 0; j < 4; j++)
                bp[j].f = *(const float2*)&Bs[kk][tx * 8 + 2 * j];
            #pragma unroll
            for (int i = 0; i < 8; i++)
                #pragma unroll
                for (int j = 0; j < 4; j++)
                    ffma2(acc[i][j].u, ad[i].u, bp[j].u);
        }
    }

    // epilogue
    #pragma unroll
    for (int i = 0; i < 8; i++) {
        int m = m0 + ty * 8 + i;
        if (m < NNODES) {
            float4* o = (float4*)(Yb + (size_t)m * DIM + n0 + tx * 8);
            o[0] = make_float4(acc[i][0].f.x, acc[i][0].f.y, acc[i][1].f.x, acc[i][1].f.y);
            o[1] = make_float4(acc[i][2].f.x, acc[i][2].f.y, acc[i][3].f.x, acc[i][3].f.y);
        }
    }
}

// ---------------------------------------------------------------------------
// K2: fused combine + edge scatter.  One warp per edge:
//     out[dst] += norm_e * sum_b w_comp[etype_e, b] * Y[b][src_e]
//     Edge scalars loaded once by lane 0, broadcast via shfl.
//     w_comp (16x8 = 128 floats) cached in shared memory per block.
// ---------------------------------------------------------------------------
__global__ __launch_bounds__(256)
void scatter_kernel(const int* __restrict__ src,
                    const int* __restrict__ dst,
                    const int* __restrict__ et,
                    const float* __restrict__ norm,
                    const float* __restrict__ w_comp,
                    float* __restrict__ out) {
    __shared__ float wc[NRELS * NBASES];
    if (threadIdx.x < NRELS * NBASES) wc[threadIdx.x] = w_comp[threadIdx.x];
    __syncthreads();

    int e = (int)(((size_t)blockIdx.x * blockDim.x + threadIdx.x) >> 5);
    int lane = threadIdx.x & 31;
    if (e >= NEDGES) return;

    int s, d, r;
    float nm;
    if (lane == 0) {
        s  = __ldg(src + e);
        d  = __ldg(dst + e);
        r  = __ldg(et + e);
        nm = __ldg(norm + e);
    }
    s  = __shfl_sync(0xffffffffu, s, 0);
    d  = __shfl_sync(0xffffffffu, d, 0);
    r  = __shfl_sync(0xffffffffu, r, 0);
    nm = __shfl_sync(0xffffffffu, nm, 0);

    const float* cb = &wc[r * NBASES];

    // Each lane owns columns [lane*4, lane*4+4) and [128 + lane*4, ...).
    float4 a0 = make_float4(0.f, 0.f, 0.f, 0.f);
    float4 a1 = make_float4(0.f, 0.f, 0.f, 0.f);
    const size_t rowOff = (size_t)s * DIM;

    #pragma unroll
    for (int b = 0; b < NBASES; b++) {
        const float4* yrow = (const float4*)(g_Y + (size_t)b * NNODES * DIM + rowOff);
        float c = cb[b];
        float4 v0 = __ldg(&yrow[lane]);
        float4 v1 = __ldg(&yrow[lane + 32]);
        a0.x = fmaf(c, v0.x, a0.x); a0.y = fmaf(c, v0.y, a0.y);
        a0.z = fmaf(c, v0.z, a0.z); a0.w = fmaf(c, v0.w, a0.w);
        a1.x = fmaf(c, v1.x, a1.x); a1.y = fmaf(c, v1.y, a1.y);
        a1.z = fmaf(c, v1.z, a1.z); a1.w = fmaf(c, v1.w, a1.w);
    }

    a0.x *= nm; a0.y *= nm; a0.z *= nm; a0.w *= nm;
    a1.x *= nm; a1.y *= nm; a1.z *= nm; a1.w *= nm;

    float4* orow = (float4*)(out + (size_t)d * DIM);
    red_add_v4(&orow[lane],      a0);
    red_add_v4(&orow[lane + 32], a1);
    if (lane == 0) atomicAdd(&g_deg[d], 1.0f);
}

// ---------------------------------------------------------------------------
// K3: finalize  out[n][d] = (deg>0 ? out[n][d]/deg : 0) + bias[d]
// ---------------------------------------------------------------------------
__global__ __launch_bounds__(256)
void finalize_kernel(const float* __restrict__ bias, float4* __restrict__ out) {
    size_t idx = (size_t)blockIdx.x * blockDim.x + threadIdx.x;   // N*D/4
    const size_t tot4 = (size_t)NNODES * DIM / 4;
    if (idx >= tot4) return;
    int n  = (int)(idx >> 6);     // 64 float4 per row
    int d4 = (int)(idx & 63);
    float cnt = g_deg[n];
    float inv = (cnt > 0.f) ? (1.0f / cnt) : 0.0f;
    float4 v = out[idx];
    float4 bb = ((const float4*)bias)[d4];
    v.x = fmaf(v.x, inv, bb.x);
    v.y = fmaf(v.y, inv, bb.y);
    v.z = fmaf(v.z, inv, bb.z);
    v.w = fmaf(v.w, inv, bb.w);
    out[idx] = v;
}

// ---------------------------------------------------------------------------
// kernel_launch
// Inputs (metadata order): node_ids[i32,N], src[i32,E], dst[i32,E],
//   etypes[i32,E], norm[f32,E], emb[f32,N*D], basis[f32,B*D*D],
//   w_comp[f32,R*B], h_bias[f32,D].  Output: f32 [N, D].
// ---------------------------------------------------------------------------
extern "C" void kernel_launch(void* const* d_in, const int* in_sizes, int n_in,
                              void* d_out, int out_size) {
    const int*   node_ids = (const int*)  d_in[0];
    const int*   src      = (const int*)  d_in[1];
    const int*   dst      = (const int*)  d_in[2];
    const int*   etypes   = (const int*)  d_in[3];
    const float* norm     = (const float*)d_in[4];
    const float* emb      = (const float*)d_in[5];
    const float* basis    = (const float*)d_in[6];
    const float* w_comp   = (const float*)d_in[7];
    const float* h_bias   = (const float*)d_in[8];
    float* out = (float*)d_out;

    const int tot4 = NNODES * DIM / 4;              // 6,400,000
    const int blk4 = (tot4 + 255) / 256;            // 25,000

    // K0: zero accumulators
    zero_kernel<<<blk4, 256>>>((float4*)out);

    // K1: Y[b] = emb @ basis[b]
    dim3 gg((NNODES + 127) / 128, DIM / 128, NBASES);   // (782, 2, 8)
    gemm_basis_kernel<<<gg, 256>>>(emb, node_ids, basis);

    // K2: fused combine + edge scatter (warp per edge)
    scatter_kernel<<<(NEDGES * 32 + 255) / 256, 256>>>(src, dst, etypes, norm,
                                                       w_comp, out);

    // K3: mean + bias
    finalize_kernel<<<blk4, 256>>>(h_bias, (float4*)out);
}

// round 7
// speedup vs baseline: 2.1290x; 2.1290x over previous
#include <cuda_runtime.h>
#include <cuda_bf16.h>
#include <cstdint>

// Problem constants
#define NNODES 100000
#define DIM    256
#define NBASES 8
#define NRELS  16
#define NEDGES 800000

// ---------------------------------------------------------------------------
// Static device scratch (~925 MB total; 2.46 GB crashed the container, 930 MB ok)
// ---------------------------------------------------------------------------
__device__ float           g_Y[(size_t)NBASES * NNODES * DIM]; // 819.2 MB
__device__ __nv_bfloat16   g_Ah[(size_t)NNODES * DIM];         // 51.2 MB hi(emb[node_ids])
__device__ __nv_bfloat16   g_Al[(size_t)NNODES * DIM];         // 51.2 MB lo residual
__device__ __nv_bfloat16   g_Bth[(size_t)NBASES * DIM * DIM];  // 1 MB hi(basis^T) [b][n][k]
__device__ __nv_bfloat16   g_Btl[(size_t)NBASES * DIM * DIM];  // 1 MB lo residual
__device__ int   g_cnt[NNODES];        // out-degree (src histogram)
__device__ int   g_dcnt[NNODES];       // in-degree  (dst histogram)
__device__ int   g_start[NNODES];      // CSR row starts (exclusive scan of cnt)
__device__ int   g_cur[NNODES];        // fill cursors
__device__ int   g_perm[NEDGES];       // edge ids sorted by src

// ---------------------------------------------------------------------------
// PTX helpers (compute_100-safe: ldmatrix + mma.sync only, NO tcgen05)
// ---------------------------------------------------------------------------
__device__ __forceinline__ uint32_t smem_to_u32(const void* p) {
    uint32_t a;
    asm("{ .reg .u64 t; cvta.to.shared.u64 t, %1; cvt.u32.u64 %0, t; }" : "=r"(a) : "l"(p));
    return a;
}

__device__ __forceinline__ void ldsm_x4(uint32_t& r0, uint32_t& r1, uint32_t& r2,
                                        uint32_t& r3, uint32_t addr) {
    asm volatile("ldmatrix.sync.aligned.m8n8.x4.shared.b16 {%0,%1,%2,%3}, [%4];"
                 : "=r"(r0), "=r"(r1), "=r"(r2), "=r"(r3) : "r"(addr));
}
__device__ __forceinline__ void ldsm_x2(uint32_t& r0, uint32_t& r1, uint32_t addr) {
    asm volatile("ldmatrix.sync.aligned.m8n8.x2.shared.b16 {%0,%1}, [%2];"
                 : "=r"(r0), "=r"(r1) : "r"(addr));
}
__device__ __forceinline__ void mma_bf16(float* c, const uint32_t* a, const uint32_t* b) {
    asm volatile("mma.sync.aligned.m16n8k16.row.col.f32.bf16.bf16.f32 "
                 "{%0,%1,%2,%3}, {%4,%5,%6,%7}, {%8,%9}, {%0,%1,%2,%3};"
                 : "+f"(c[0]), "+f"(c[1]), "+f"(c[2]), "+f"(c[3])
                 : "r"(a[0]), "r"(a[1]), "r"(a[2]), "r"(a[3]), "r"(b[0]), "r"(b[1]));
}
__device__ __forceinline__ void red_add_v4(float4* p, float4 v) {
    asm volatile("red.global.add.v4.f32 [%0], {%1, %2, %3, %4};"
                 :: "l"(p), "f"(v.x), "f"(v.y), "f"(v.z), "f"(v.w) : "memory");
}

// ---------------------------------------------------------------------------
// K0: zero output accumulator and histograms
// ---------------------------------------------------------------------------
__global__ void zero_kernel(float4* __restrict__ out) {
    size_t i = (size_t)blockIdx.x * blockDim.x + threadIdx.x;
    const size_t tot4 = (size_t)NNODES * DIM / 4;
    if (i < tot4) out[i] = make_float4(0.f, 0.f, 0.f, 0.f);
    if (i < NNODES) { g_cnt[i] = 0; g_dcnt[i] = 0; }
}

// ---------------------------------------------------------------------------
// K1a: split A = emb[node_ids] into hi/lo bf16
// ---------------------------------------------------------------------------
__global__ __launch_bounds__(256)
void split_a_kernel(const float* __restrict__ emb, const int* __restrict__ node_ids) {
    size_t t = (size_t)blockIdx.x * blockDim.x + threadIdx.x;  // over N*D/4
    const size_t tot = (size_t)NNODES * (DIM / 4);
    if (t >= tot) return;
    int row = (int)(t >> 6);
    int c4  = (int)(t & 63);
    int nid = node_ids[row];
    float4 v = ((const float4*)(emb + (size_t)nid * DIM))[c4];
    __nv_bfloat16 hx = __float2bfloat16(v.x), hy = __float2bfloat16(v.y);
    __nv_bfloat16 hz = __float2bfloat16(v.z), hw = __float2bfloat16(v.w);
    __nv_bfloat16 lx = __float2bfloat16(v.x - __bfloat162float(hx));
    __nv_bfloat16 ly = __float2bfloat16(v.y - __bfloat162float(hy));
    __nv_bfloat16 lz = __float2bfloat16(v.z - __bfloat162float(hz));
    __nv_bfloat16 lw = __float2bfloat16(v.w - __bfloat162float(hw));
    __nv_bfloat162* ph = (__nv_bfloat162*)g_Ah;
    __nv_bfloat162* pl = (__nv_bfloat162*)g_Al;
    ph[t * 2]     = __nv_bfloat162{hx, hy};
    ph[t * 2 + 1] = __nv_bfloat162{hz, hw};
    pl[t * 2]     = __nv_bfloat162{lx, ly};
    pl[t * 2 + 1] = __nv_bfloat162{lz, lw};
}

// ---------------------------------------------------------------------------
// K1b: split + transpose basis -> Bt[b][n][k] (hi/lo)
// ---------------------------------------------------------------------------
__global__ __launch_bounds__(256)
void split_b_kernel(const float* __restrict__ basis) {
    int idx = blockIdx.x * blockDim.x + threadIdx.x;   // over 8*256*256
    if (idx >= NBASES * DIM * DIM) return;
    int b = idx >> 16;
    int n = (idx >> 8) & 255;
    int k = idx & 255;
    float x = basis[(size_t)b * DIM * DIM + (size_t)k * DIM + n];
    __nv_bfloat16 h = __float2bfloat16(x);
    __nv_bfloat16 l = __float2bfloat16(x - __bfloat162float(h));
    g_Bth[idx] = h;
    g_Btl[idx] = l;
}

// ---------------------------------------------------------------------------
// K2: bf16 mma.sync GEMM.  Y[b] = Ah Bh + Al Bh + Ah Bl  (fp32 accum)
// CTA tile 128x128, 8 warps (4m x 2n), warp tile 32x64, k-chunk 64.
// SMEM rows padded to 72 bf16 (144B) -> conflict-free ldmatrix.
// grid (16 = basis*2+ntile, 782 mtiles)
// ---------------------------------------------------------------------------
#define PAD       72
#define SPLIT_SZ  (128 * PAD)            // bf16 elems per split per tile
#define SM_A_BYTES (2 * SPLIT_SZ * 2)    // 36864
#define SM_TOTAL_GEMM (2 * SM_A_BYTES)   // 73728

__global__ __launch_bounds__(256)
void gemm_mma_kernel() {
    extern __shared__ __nv_bfloat16 smem[];
    __nv_bfloat16* smA = smem;                         // [split][row 0..127][PAD]
    __nv_bfloat16* smB = smem + 2 * SPLIT_SZ;          // [split][nrow 0..127][PAD]
    const uint32_t smAu = smem_to_u32(smA);
    const uint32_t smBu = smem_to_u32(smB);

    const int tid  = threadIdx.x;
    const int lane = tid & 31;
    const int w    = tid >> 5;
    const int mw   = w >> 1;        // 0..3
    const int nw   = w & 1;         // 0..1

    const int basis = blockIdx.x >> 1;
    const int n0    = (blockIdx.x & 1) * 128;
    const int m0    = blockIdx.y * 128;

    float acc[2][8][4];
    #pragma unroll
    for (int i = 0; i < 2; i++)
        #pragma unroll
        for (int j = 0; j < 8; j++)
            #pragma unroll
            for (int k = 0; k < 4; k++) acc[i][j][k] = 0.f;

    const __nv_bfloat16* gBh = g_Bth + (size_t)basis * DIM * DIM;
    const __nv_bfloat16* gBl = g_Btl + (size_t)basis * DIM * DIM;

    for (int kc = 0; kc < 4; kc++) {
        if (kc) __syncthreads();
        const int kbase = kc * 64;

        // ---- load A (both splits): 2048 uint4, 8 per thread ----
        #pragma unroll
        for (int it = 0; it < 8; it++) {
            int i = it * 256 + tid;
            int split = i >> 10;
            int rem = i & 1023;
            int row = rem >> 3;
            int kg  = (rem & 7) * 8;
            const __nv_bfloat16* ga = split ? g_Al : g_Ah;
            int rowg = m0 + row; if (rowg >= NNODES) rowg = NNODES - 1;
            uint4 v = *(const uint4*)(ga + (size_t)rowg * DIM + kbase + kg);
            *(uint4*)(smA + split * SPLIT_SZ + row * PAD + kg) = v;
        }
        // ---- load B (both splits): rows n0..n0+127 ----
        #pragma unroll
        for (int it = 0; it < 8; it++) {
            int i = it * 256 + tid;
            int split = i >> 10;
            int rem = i & 1023;
            int row = rem >> 3;
            int kg  = (rem & 7) * 8;
            const __nv_bfloat16* gb = split ? gBl : gBh;
            uint4 v = *(const uint4*)(gb + (size_t)(n0 + row) * DIM + kbase + kg);
            *(uint4*)(smB + split * SPLIT_SZ + row * PAD + kg) = v;
        }
        __syncthreads();

        // ---- compute: 4 k16 steps ----
        #pragma unroll
        for (int kk = 0; kk < 4; kk++) {
            const int kof = kk * 16 + ((lane >> 4) << 3);     // A k-offset per lane
            uint32_t ah[2][4], al[2][4];
            #pragma unroll
            for (int mi = 0; mi < 2; mi++) {
                int row = mw * 32 + mi * 16 + (lane & 15);
                uint32_t adr = smAu + (uint32_t)(row * PAD + kof) * 2;
                ldsm_x4(ah[mi][0], ah[mi][1], ah[mi][2], ah[mi][3], adr);
                ldsm_x4(al[mi][0], al[mi][1], al[mi][2], al[mi][3],
                        adr + SPLIT_SZ * 2);
            }
            const int bko = kk * 16 + (((lane >> 3) & 1) << 3);
            #pragma unroll
            for (int nt = 0; nt < 8; nt++) {
                int nrow = nw * 64 + nt * 8 + (lane & 7);
                uint32_t adr = smBu + (uint32_t)(nrow * PAD + bko) * 2;
                uint32_t bh[2], bl[2];
                ldsm_x2(bh[0], bh[1], adr);
                ldsm_x2(bl[0], bl[1], adr + SPLIT_SZ * 2);
                #pragma unroll
                for (int mi = 0; mi < 2; mi++) {
                    mma_bf16(acc[mi][nt], ah[mi], bh);
                    mma_bf16(acc[mi][nt], al[mi], bh);
                    mma_bf16(acc[mi][nt], ah[mi], bl);
                }
            }
        }
    }

    // ---- epilogue: fragment c layout -> global float2 stores ----
    float* Yb = g_Y + (size_t)basis * NNODES * DIM;
    const int qrow = lane >> 2;
    const int qcol = (lane & 3) * 2;
    #pragma unroll
    for (int mi = 0; mi < 2; mi++) {
        #pragma unroll
        for (int nt = 0; nt < 8; nt++) {
            float* c = acc[mi][nt];
            int col  = n0 + nw * 64 + nt * 8 + qcol;
            int row0 = m0 + mw * 32 + mi * 16 + qrow;
            int row1 = row0 + 8;
            if (row0 < NNODES) {
                float2 v = make_float2(c[0], c[1]);
                *(float2*)(Yb + (size_t)row0 * DIM + col) = v;
            }
            if (row1 < NNODES) {
                float2 v = make_float2(c[2], c[3]);
                *(float2*)(Yb + (size_t)row1 * DIM + col) = v;
            }
        }
    }
}

// ---------------------------------------------------------------------------
// K3: histograms (src out-degree, dst in-degree)
// ---------------------------------------------------------------------------
__global__ __launch_bounds__(256)
void hist_kernel(const int* __restrict__ src, const int* __restrict__ dst) {
    int e = blockIdx.x * blockDim.x + threadIdx.x;
    if (e < NEDGES) {
        atomicAdd(&g_cnt[src[e]], 1);
        atomicAdd(&g_dcnt[dst[e]], 1);
    }
}

// ---------------------------------------------------------------------------
// K4: exclusive scan of g_cnt -> g_start, g_cur (single block)
// ---------------------------------------------------------------------------
__global__ __launch_bounds__(1024)
void scan_kernel() {
    __shared__ int warp_sums[32];
    __shared__ int s_carry;
    int tid = threadIdx.x, lane = tid & 31, wid = tid >> 5;
    if (tid == 0) s_carry = 0;
    __syncthreads();
    for (int base = 0; base < NNODES; base += 1024) {
        int i = base + tid;
        int v = (i < NNODES) ? g_cnt[i] : 0;
        int x = v;
        #pragma unroll
        for (int d = 1; d < 32; d <<= 1) {
            int y = __shfl_up_sync(0xffffffffu, x, d);
            if (lane >= d) x += y;
        }
        if (lane == 31) warp_sums[wid] = x;
        __syncthreads();
        if (wid == 0) {
            int s = warp_sums[lane];
            #pragma unroll
            for (int d = 1; d < 32; d <<= 1) {
                int y = __shfl_up_sync(0xffffffffu, s, d);
                if (lane >= d) s += y;
            }
            warp_sums[lane] = s;
        }
        __syncthreads();
        int woff = (wid > 0) ? warp_sums[wid - 1] : 0;
        int excl = x + woff - v + s_carry;
        if (i < NNODES) { g_start[i] = excl; g_cur[i] = excl; }
        int block_total = warp_sums[31];
        __syncthreads();
        if (tid == 0) s_carry += block_total;
        __syncthreads();
    }
}

// ---------------------------------------------------------------------------
// K5: fill permutation (counting-sort scatter phase)
// ---------------------------------------------------------------------------
__global__ __launch_bounds__(256)
void fill_kernel(const int* __restrict__ src) {
    int e = blockIdx.x * blockDim.x + threadIdx.x;
    if (e >= NEDGES) return;
    int pos = atomicAdd(&g_cur[src[e]], 1);
    g_perm[pos] = e;
}

// ---------------------------------------------------------------------------
// K6: warp-per-src scatter.  Load the 8 Y rows of src once into registers,
//     serve all out-edges from registers:
//     out[dst] += norm_e * sum_b w_comp[etype_e, b] * Y[b][src]
// ---------------------------------------------------------------------------
__global__ __launch_bounds__(256)
void scatter_kernel(const int* __restrict__ dst,
                    const int* __restrict__ et,
                    const float* __restrict__ norm,
                    const float* __restrict__ w_comp,
                    float* __restrict__ out) {
    __shared__ float wc[NRELS * NBASES];
    if (threadIdx.x < NRELS * NBASES) wc[threadIdx.x] = w_comp[threadIdx.x];
    __syncthreads();

    int s = (int)(((size_t)blockIdx.x * blockDim.x + threadIdx.x) >> 5);
    int lane = threadIdx.x & 31;
    if (s >= NNODES) return;

    int start = g_start[s];
    int cnt   = g_cnt[s];
    if (cnt == 0) return;

    // Resident Y rows: lane owns cols [lane*4, +4) and [128+lane*4, +4)
    float4 y0[NBASES], y1[NBASES];
    const size_t rowOff = (size_t)s * DIM;
    #pragma unroll
    for (int b = 0; b < NBASES; b++) {
        const float4* yrow = (const float4*)(g_Y + (size_t)b * NNODES * DIM + rowOff);
        y0[b] = __ldg(&yrow[lane]);
        y1[b] = __ldg(&yrow[lane + 32]);
    }

    for (int base = 0; base < cnt; base += 32) {
        int n_here = min(32, cnt - base);
        int d = 0, r = 0; float nm = 0.f;
        if (lane < n_here) {
            int e = __ldg(g_perm + start + base + lane);
            d  = __ldg(dst + e);
            r  = __ldg(et + e);
            nm = __ldg(norm + e);
        }
        for (int i = 0; i < n_here; i++) {
            int   di = __shfl_sync(0xffffffffu, d, i);
            int   ri = __shfl_sync(0xffffffffu, r, i);
            float ni = __shfl_sync(0xffffffffu, nm, i);
            const float* cb = &wc[ri * NBASES];
            float4 a0 = make_float4(0.f, 0.f, 0.f, 0.f);
            float4 a1 = make_float4(0.f, 0.f, 0.f, 0.f);
            #pragma unroll
            for (int b = 0; b < NBASES; b++) {
                float c = cb[b];
                a0.x = fmaf(c, y0[b].x, a0.x); a0.y = fmaf(c, y0[b].y, a0.y);
                a0.z = fmaf(c, y0[b].z, a0.z); a0.w = fmaf(c, y0[b].w, a0.w);
                a1.x = fmaf(c, y1[b].x, a1.x); a1.y = fmaf(c, y1[b].y, a1.y);
                a1.z = fmaf(c, y1[b].z, a1.z); a1.w = fmaf(c, y1[b].w, a1.w);
            }
            a0.x *= ni; a0.y *= ni; a0.z *= ni; a0.w *= ni;
            a1.x *= ni; a1.y *= ni; a1.z *= ni; a1.w *= ni;
            float4* orow = (float4*)(out + (size_t)di * DIM);
            red_add_v4(&orow[lane],      a0);
            red_add_v4(&orow[lane + 32], a1);
        }
    }
}

// ---------------------------------------------------------------------------
// K7: finalize  out = (deg>0 ? out/deg : 0) + bias
// ---------------------------------------------------------------------------
__global__ __launch_bounds__(256)
void finalize_kernel(const float* __restrict__ bias, float4* __restrict__ out) {
    size_t idx = (size_t)blockIdx.x * blockDim.x + threadIdx.x;
    const size_t tot4 = (size_t)NNODES * DIM / 4;
    if (idx >= tot4) return;
    int n  = (int)(idx >> 6);
    int d4 = (int)(idx & 63);
    int cnt = g_dcnt[n];
    float inv = (cnt > 0) ? (1.0f / (float)cnt) : 0.0f;
    float4 v = out[idx];
    float4 bb = ((const float4*)bias)[d4];
    v.x = fmaf(v.x, inv, bb.x);
    v.y = fmaf(v.y, inv, bb.y);
    v.z = fmaf(v.z, inv, bb.z);
    v.w = fmaf(v.w, inv, bb.w);
    out[idx] = v;
}

// ---------------------------------------------------------------------------
// kernel_launch
// Inputs (metadata order): node_ids[i32,N], src[i32,E], dst[i32,E],
//   etypes[i32,E], norm[f32,E], emb[f32,N*D], basis[f32,B*D*D],
//   w_comp[f32,R*B], h_bias[f32,D].  Output: f32 [N, D].
// ---------------------------------------------------------------------------
extern "C" void kernel_launch(void* const* d_in, const int* in_sizes, int n_in,
                              void* d_out, int out_size) {
    const int*   node_ids = (const int*)  d_in[0];
    const int*   src      = (const int*)  d_in[1];
    const int*   dst      = (const int*)  d_in[2];
    const int*   etypes   = (const int*)  d_in[3];
    const float* norm     = (const float*)d_in[4];
    const float* emb      = (const float*)d_in[5];
    const float* basis    = (const float*)d_in[6];
    const float* w_comp   = (const float*)d_in[7];
    const float* h_bias   = (const float*)d_in[8];
    float* out = (float*)d_out;

    const int tot4 = NNODES * DIM / 4;
    const int blk4 = (tot4 + 255) / 256;

    static int smem_set = 0;
    if (!smem_set) {
        cudaFuncSetAttribute(gemm_mma_kernel,
                             cudaFuncAttributeMaxDynamicSharedMemorySize,
                             SM_TOTAL_GEMM);
        smem_set = 1;
    }

    zero_kernel<<<blk4, 256>>>((float4*)out);
    split_a_kernel<<<blk4, 256>>>(emb, node_ids);
    split_b_kernel<<<(NBASES * DIM * DIM + 255) / 256, 256>>>(basis);

    hist_kernel<<<(NEDGES + 255) / 256, 256>>>(src, dst);
    scan_kernel<<<1, 1024>>>();
    fill_kernel<<<(NEDGES + 255) / 256, 256>>>(src);

    dim3 gg(16, (NNODES + 127) / 128);      // x = basis*2 + ntile (fast), y = mtile
    gemm_mma_kernel<<<gg, 256, SM_TOTAL_GEMM>>>();

    scatter_kernel<<<(NNODES * 32 + 255) / 256, 256>>>(dst, etypes, norm, w_comp, out);
    finalize_kernel<<<blk4, 256>>>(h_bias, (float4*)out);
}